// round 3
// baseline (speedup 1.0000x reference)
#include <cuda_runtime.h>
#include <cuda_bf16.h>
#include <math_constants.h>

// Problem constants
#define BATCH 8
#define SEQ   2048
#define EMB   768

// Scratch (device globals: allowed; no runtime allocation)
__device__ float g_v[(long long)BATCH * SEQ * EMB];
__device__ float g_k[(long long)BATCH * SEQ * EMB];
__device__ float g_q[(long long)BATCH * SEQ * EMB];
__device__ float g_scores[(long long)BATCH * SEQ * SEQ];
__device__ float g_ctx[(long long)BATCH * SEQ * EMB];

// ---------------------------------------------------------------------------
// Tiled SGEMM: C[m,n] = alpha * sum_k A[m,k] * B'[k,n]  (+ bias[n])
//   TRANSB=true : B is [N,K] row-major (B'[k,n] = B[n,k])  -- "x @ W.T" form
//   TRANSB=false: B is [K,N] row-major                     -- "attn @ v" form
// Batched via blockIdx.z with element strides sA,sB,sC.
// Requires M%128==0, N%128==0, K%16==0 (true for all uses here).
// ---------------------------------------------------------------------------
#define BM 128
#define BN 128
#define BKK 16
#define TM 8
#define TN 8

template <bool TRANSB, bool BIAS>
__global__ __launch_bounds__(256, 2)
void sgemm_kernel(const float* __restrict__ A, const float* __restrict__ B,
                  const float* __restrict__ bias, float* __restrict__ C,
                  int M, int N, int K,
                  long long sA, long long sB, long long sC, float alpha)
{
    __shared__ float As[BKK][BM + 4];
    __shared__ float Bs[BKK][BN + 4];

    const long long bz = blockIdx.z;
    A += bz * sA;
    B += bz * sB;
    C += bz * sC;

    const int tid  = threadIdx.x;
    const int row0 = blockIdx.y * BM;
    const int col0 = blockIdx.x * BN;
    const int tx   = tid & 15;   // 16 col-groups
    const int ty   = tid >> 4;   // 16 row-groups

    float acc[TM][TN];
#pragma unroll
    for (int i = 0; i < TM; i++)
#pragma unroll
        for (int j = 0; j < TN; j++) acc[i][j] = 0.f;

    for (int k0 = 0; k0 < K; k0 += BKK) {
        // --- load A tile: BM x BKK (128x16) = 512 float4, 2 per thread
#pragma unroll
        for (int it = 0; it < 2; it++) {
            int idx = tid + it * 256;       // 0..511
            int r   = idx >> 2;             // row in tile
            int c4  = idx & 3;              // which float4 in the 16-wide row
            float4 v = *reinterpret_cast<const float4*>(
                &A[(long long)(row0 + r) * K + k0 + c4 * 4]);
            As[c4 * 4 + 0][r] = v.x;
            As[c4 * 4 + 1][r] = v.y;
            As[c4 * 4 + 2][r] = v.z;
            As[c4 * 4 + 3][r] = v.w;
        }
        // --- load B tile
        if (TRANSB) {
            // B is [N,K]: load BN x BKK rows, transpose into Bs[k][n]
#pragma unroll
            for (int it = 0; it < 2; it++) {
                int idx = tid + it * 256;
                int r   = idx >> 2;         // n within tile
                int c4  = idx & 3;
                float4 v = *reinterpret_cast<const float4*>(
                    &B[(long long)(col0 + r) * K + k0 + c4 * 4]);
                Bs[c4 * 4 + 0][r] = v.x;
                Bs[c4 * 4 + 1][r] = v.y;
                Bs[c4 * 4 + 2][r] = v.z;
                Bs[c4 * 4 + 3][r] = v.w;
            }
        } else {
            // B is [K,N]: load BKK x BN rows directly
#pragma unroll
            for (int it = 0; it < 2; it++) {
                int idx = tid + it * 256;
                int r   = idx >> 5;         // k row (16 rows of 32 float4)
                int c4  = idx & 31;
                float4 v = *reinterpret_cast<const float4*>(
                    &B[(long long)(k0 + r) * N + col0 + c4 * 4]);
                *reinterpret_cast<float4*>(&Bs[r][c4 * 4]) = v;
            }
        }
        __syncthreads();

#pragma unroll
        for (int k = 0; k < BKK; k++) {
            float a[TM], b[TN];
#pragma unroll
            for (int i = 0; i < TM; i++) a[i] = As[k][ty * TM + i];
#pragma unroll
            for (int j = 0; j < TN; j++) b[j] = Bs[k][tx * TN + j];
#pragma unroll
            for (int i = 0; i < TM; i++)
#pragma unroll
                for (int j = 0; j < TN; j++) acc[i][j] += a[i] * b[j];
        }
        __syncthreads();
    }

    // --- epilogue: scale, optional bias, vectorized store
#pragma unroll
    for (int i = 0; i < TM; i++) {
        int r = row0 + ty * TM + i;
        int c = col0 + tx * TN;
        float4 o0, o1;
        o0.x = acc[i][0] * alpha; o0.y = acc[i][1] * alpha;
        o0.z = acc[i][2] * alpha; o0.w = acc[i][3] * alpha;
        o1.x = acc[i][4] * alpha; o1.y = acc[i][5] * alpha;
        o1.z = acc[i][6] * alpha; o1.w = acc[i][7] * alpha;
        if (BIAS) {
            o0.x += bias[c + 0]; o0.y += bias[c + 1];
            o0.z += bias[c + 2]; o0.w += bias[c + 3];
            o1.x += bias[c + 4]; o1.y += bias[c + 5];
            o1.z += bias[c + 6]; o1.w += bias[c + 7];
        }
        *reinterpret_cast<float4*>(&C[(long long)r * N + c + 0]) = o0;
        *reinterpret_cast<float4*>(&C[(long long)r * N + c + 4]) = o1;
    }
}

// ---------------------------------------------------------------------------
// Masked softmax over rows of scores[b, q, :], in place.
// mask is [B, 1, S] int32; mask==0 -> -inf before softmax (-> 0 after).
// grid = (S, B), block = 256 threads, each thread owns 8 entries.
// ---------------------------------------------------------------------------
__inline__ __device__ float warp_max(float v) {
#pragma unroll
    for (int o = 16; o > 0; o >>= 1) v = fmaxf(v, __shfl_xor_sync(0xffffffffu, v, o));
    return v;
}
__inline__ __device__ float warp_sum(float v) {
#pragma unroll
    for (int o = 16; o > 0; o >>= 1) v += __shfl_xor_sync(0xffffffffu, v, o);
    return v;
}

__global__ __launch_bounds__(256)
void softmax_mask_kernel(float* __restrict__ scores, const int* __restrict__ mask)
{
    const int b = blockIdx.y;
    const int q = blockIdx.x;
    float* row = scores + ((long long)b * SEQ + q) * SEQ;
    const int* mrow = mask + (long long)b * SEQ;

    const int tid = threadIdx.x;
    float vals[8];
    float mx = -CUDART_INF_F;
#pragma unroll
    for (int i = 0; i < 8; i++) {
        int idx = tid + i * 256;
        float v = row[idx];
        if (mrow[idx] == 0) v = -CUDART_INF_F;
        vals[i] = v;
        mx = fmaxf(mx, v);
    }

    __shared__ float sred[8];
    float wm = warp_max(mx);
    if ((tid & 31) == 0) sred[tid >> 5] = wm;
    __syncthreads();
    float bm = (tid < 8) ? sred[tid] : -CUDART_INF_F;
    bm = warp_max(bm);
    __shared__ float s_bm;
    if (tid == 0) s_bm = bm;
    __syncthreads();
    bm = s_bm;

    float sum = 0.f;
#pragma unroll
    for (int i = 0; i < 8; i++) {
        float e = (vals[i] == -CUDART_INF_F) ? 0.f : expf(vals[i] - bm);
        vals[i] = e;
        sum += e;
    }
    float ws = warp_sum(sum);
    if ((tid & 31) == 0) sred[tid >> 5] = ws;
    __syncthreads();
    float bs = (tid < 8) ? sred[tid] : 0.f;
    bs = warp_sum(bs);
    __shared__ float s_bs;
    if (tid == 0) s_bs = bs;
    __syncthreads();
    float inv = 1.f / s_bs;

#pragma unroll
    for (int i = 0; i < 8; i++) {
        int idx = tid + i * 256;
        row[idx] = vals[i] * inv;
    }
}

// ---------------------------------------------------------------------------
// kernel_launch
// inputs (metadata order): value, key, query, mask, Wv, Wk, Wq, Wo, bo
// ---------------------------------------------------------------------------
extern "C" void kernel_launch(void* const* d_in, const int* in_sizes, int n_in,
                              void* d_out, int out_size)
{
    const float* value = (const float*)d_in[0];
    const float* key   = (const float*)d_in[1];
    const float* query = (const float*)d_in[2];
    const int*   mask  = (const int*)d_in[3];
    const float* Wv    = (const float*)d_in[4];
    const float* Wk    = (const float*)d_in[5];
    const float* Wq    = (const float*)d_in[6];
    const float* Wo    = (const float*)d_in[7];
    const float* bo    = (const float*)d_in[8];
    float* out = (float*)d_out;

    float *pv, *pk, *pq, *ps, *pc;
    cudaGetSymbolAddress((void**)&pv, g_v);
    cudaGetSymbolAddress((void**)&pk, g_k);
    cudaGetSymbolAddress((void**)&pq, g_q);
    cudaGetSymbolAddress((void**)&ps, g_scores);
    cudaGetSymbolAddress((void**)&pc, g_ctx);

    const int MBS = BATCH * SEQ;  // 16384
    const long long SE = (long long)SEQ * EMB;
    const long long SS = (long long)SEQ * SEQ;

    // 1-3) projections: [16384 x 768] = X[16384x768] @ W^T[768x768]
    {
        dim3 grid(EMB / BN, MBS / BM, 1);
        sgemm_kernel<true, false><<<grid, 256>>>(value, Wv, nullptr, pv,
            MBS, EMB, EMB, 0, 0, 0, 1.0f);
        sgemm_kernel<true, false><<<grid, 256>>>(key, Wk, nullptr, pk,
            MBS, EMB, EMB, 0, 0, 0, 1.0f);
        // fold the (1/sqrt(E))*(1/sqrt(E)) score scaling into q
        sgemm_kernel<true, false><<<grid, 256>>>(query, Wq, nullptr, pq,
            MBS, EMB, EMB, 0, 0, 0, 1.0f / (float)EMB);
    }

    // 4) scores[b] = q[b] @ k[b]^T   (batched, 2048x2048x768)
    {
        dim3 grid(SEQ / BN, SEQ / BM, BATCH);
        sgemm_kernel<true, false><<<grid, 256>>>(pq, pk, nullptr, ps,
            SEQ, SEQ, EMB, SE, SE, SS, 1.0f);
    }

    // 5) masked softmax, in place
    {
        dim3 grid(SEQ, BATCH);
        softmax_mask_kernel<<<grid, 256>>>(ps, mask);
    }

    // 6) ctx[b] = attn[b] @ v[b]   (batched, 2048x768x2048, B not transposed)
    {
        dim3 grid(EMB / BN, SEQ / BM, BATCH);
        sgemm_kernel<false, false><<<grid, 256>>>(ps, pv, nullptr, pc,
            SEQ, EMB, SEQ, SS, SE, SE, 1.0f);
    }

    // 7) out = ctx @ Wo^T + bo
    {
        dim3 grid(EMB / BN, MBS / BM, 1);
        sgemm_kernel<true, true><<<grid, 256>>>(pc, Wo, bo, out,
            MBS, EMB, EMB, 0, 0, 0, 1.0f);
    }
}

// round 4
// speedup vs baseline: 2.9916x; 2.9916x over previous
#include <cuda_runtime.h>
#include <cuda_bf16.h>
#include <math_constants.h>
#include <cstdint>

// Problem constants
#define BATCH 8
#define SEQ   2048
#define EMB   768

// Scratch (device globals: allowed; no runtime allocation)
__device__ float g_v[(long long)BATCH * SEQ * EMB];
__device__ float g_k[(long long)BATCH * SEQ * EMB];
__device__ float g_q[(long long)BATCH * SEQ * EMB];
__device__ float g_scores[(long long)BATCH * SEQ * SEQ];
__device__ float g_ctx[(long long)BATCH * SEQ * EMB];

// ---------------------------------------------------------------------------
// tf32 tensor-core GEMM: C = alpha * A @ B' (+ bias)
//   TRANSB=true : B is [N,K] row-major  (x @ W.T form, and q @ k.T)
//   TRANSB=false: B is [K,N] row-major  (attn @ v form)
// Block tile 128x128, K-tile 32, 256 threads (8 warps, 2x4 warp grid,
// each warp owns 64x32 via 4x4 grid of m16n8k8 mma).
// Requires M%128==0, N%128==0, K%32==0 (true for all uses here).
// ---------------------------------------------------------------------------
#define BM 128
#define BN 128
#define BK 32

__device__ __forceinline__ uint32_t f2tf32(float x) {
    uint32_t r;
    asm("cvt.rna.tf32.f32 %0, %1;" : "=r"(r) : "f"(x));
    return r;
}

__device__ __forceinline__ void mma8(float* c, const uint32_t* a, const uint32_t* b) {
    asm volatile(
        "mma.sync.aligned.m16n8k8.row.col.f32.tf32.tf32.f32 "
        "{%0,%1,%2,%3}, {%4,%5,%6,%7}, {%8,%9}, {%0,%1,%2,%3};\n"
        : "+f"(c[0]), "+f"(c[1]), "+f"(c[2]), "+f"(c[3])
        : "r"(a[0]), "r"(a[1]), "r"(a[2]), "r"(a[3]), "r"(b[0]), "r"(b[1]));
}

template <bool TRANSB, bool BIAS>
__global__ __launch_bounds__(256, 2)
void mma_gemm(const float* __restrict__ A, const float* __restrict__ B,
              const float* __restrict__ bias, float* __restrict__ C,
              int M, int N, int K,
              long long sA, long long sB, long long sC, float alpha)
{
    constexpr int AS_STR = BK + 4;   // [m][k], stride 36 -> frag-LDS bank = 4g+t4 (conflict-free)
    constexpr int BT_STR = BK + 4;   // [n][k], stride 36
    constexpr int BNN_STR = BN + 8;  // [k][n], stride 136 -> bank = 8*t4+g (conflict-free)

    __shared__ uint32_t As[BM * AS_STR];
    __shared__ uint32_t Bs[TRANSB ? (BN * BT_STR) : (BK * BNN_STR)];

    const long long bz = blockIdx.z;
    A += bz * sA;
    B += bz * sB;
    C += bz * sC;

    const int tid  = threadIdx.x;
    const int lane = tid & 31;
    const int wid  = tid >> 5;
    const int g    = lane >> 2;   // groupID
    const int t4   = lane & 3;    // threadID in group
    const int m0w  = (wid & 1) * 64;   // 2 warps along M
    const int n0w  = (wid >> 1) * 32;  // 4 warps along N
    const int row0 = blockIdx.y * BM;
    const int col0 = blockIdx.x * BN;

    float acc[4][4][4];
#pragma unroll
    for (int i = 0; i < 4; i++)
#pragma unroll
        for (int j = 0; j < 4; j++)
#pragma unroll
            for (int r = 0; r < 4; r++) acc[i][j][r] = 0.f;

    for (int k0 = 0; k0 < K; k0 += BK) {
        // --- A tile: 128x32 = 1024 float4, 4 per thread, converted to tf32
#pragma unroll
        for (int it = 0; it < 4; it++) {
            int idx = tid + it * 256;
            int r   = idx >> 3;      // m row
            int c4  = idx & 7;       // float4 slot in 32-wide k row
            float4 v = *reinterpret_cast<const float4*>(
                &A[(long long)(row0 + r) * K + k0 + c4 * 4]);
            uint32_t u[4] = {f2tf32(v.x), f2tf32(v.y), f2tf32(v.z), f2tf32(v.w)};
            *reinterpret_cast<uint4*>(&As[r * AS_STR + c4 * 4]) =
                *reinterpret_cast<uint4*>(u);
        }
        // --- B tile
        if (TRANSB) {
#pragma unroll
            for (int it = 0; it < 4; it++) {
                int idx = tid + it * 256;
                int r   = idx >> 3;  // n row
                int c4  = idx & 7;
                float4 v = *reinterpret_cast<const float4*>(
                    &B[(long long)(col0 + r) * K + k0 + c4 * 4]);
                uint32_t u[4] = {f2tf32(v.x), f2tf32(v.y), f2tf32(v.z), f2tf32(v.w)};
                *reinterpret_cast<uint4*>(&Bs[r * BT_STR + c4 * 4]) =
                    *reinterpret_cast<uint4*>(u);
            }
        } else {
#pragma unroll
            for (int it = 0; it < 4; it++) {
                int idx = tid + it * 256;
                int r   = idx >> 5;  // k row
                int c4  = idx & 31;  // float4 slot in 128-wide n row
                float4 v = *reinterpret_cast<const float4*>(
                    &B[(long long)(k0 + r) * N + col0 + c4 * 4]);
                uint32_t u[4] = {f2tf32(v.x), f2tf32(v.y), f2tf32(v.z), f2tf32(v.w)};
                *reinterpret_cast<uint4*>(&Bs[r * BNN_STR + c4 * 4]) =
                    *reinterpret_cast<uint4*>(u);
            }
        }
        __syncthreads();

#pragma unroll
        for (int ks = 0; ks < 4; ks++) {
            const int kk = ks * 8;
            uint32_t af[4][4];
#pragma unroll
            for (int i = 0; i < 4; i++) {
                int mr = m0w + i * 16 + g;
                af[i][0] = As[mr * AS_STR + kk + t4];
                af[i][1] = As[(mr + 8) * AS_STR + kk + t4];
                af[i][2] = As[mr * AS_STR + kk + t4 + 4];
                af[i][3] = As[(mr + 8) * AS_STR + kk + t4 + 4];
            }
            uint32_t bf[4][2];
#pragma unroll
            for (int j = 0; j < 4; j++) {
                int nc = n0w + j * 8 + g;
                if (TRANSB) {
                    bf[j][0] = Bs[nc * BT_STR + kk + t4];
                    bf[j][1] = Bs[nc * BT_STR + kk + t4 + 4];
                } else {
                    bf[j][0] = Bs[(kk + t4) * BNN_STR + nc];
                    bf[j][1] = Bs[(kk + t4 + 4) * BNN_STR + nc];
                }
            }
#pragma unroll
            for (int i = 0; i < 4; i++)
#pragma unroll
                for (int j = 0; j < 4; j++)
                    mma8(acc[i][j], af[i], bf[j]);
        }
        __syncthreads();
    }

    // --- epilogue
#pragma unroll
    for (int i = 0; i < 4; i++) {
        int r = row0 + m0w + i * 16 + g;
#pragma unroll
        for (int j = 0; j < 4; j++) {
            int c = col0 + n0w + j * 8 + t4 * 2;
            float2 v0, v1;
            v0.x = acc[i][j][0] * alpha;
            v0.y = acc[i][j][1] * alpha;
            v1.x = acc[i][j][2] * alpha;
            v1.y = acc[i][j][3] * alpha;
            if (BIAS) {
                float b0 = bias[c], b1 = bias[c + 1];
                v0.x += b0; v0.y += b1;
                v1.x += b0; v1.y += b1;
            }
            *reinterpret_cast<float2*>(&C[(long long)r * N + c]) = v0;
            *reinterpret_cast<float2*>(&C[(long long)(r + 8) * N + c]) = v1;
        }
    }
}

// ---------------------------------------------------------------------------
// Masked softmax over rows of scores[b, q, :], in place.
// mask is [B, 1, S] int32; mask==0 -> -inf before softmax (-> 0 after).
// grid = (S, B), block = 256 threads, each thread owns 8 entries.
// ---------------------------------------------------------------------------
__inline__ __device__ float warp_max(float v) {
#pragma unroll
    for (int o = 16; o > 0; o >>= 1) v = fmaxf(v, __shfl_xor_sync(0xffffffffu, v, o));
    return v;
}
__inline__ __device__ float warp_sum(float v) {
#pragma unroll
    for (int o = 16; o > 0; o >>= 1) v += __shfl_xor_sync(0xffffffffu, v, o);
    return v;
}

__global__ __launch_bounds__(256)
void softmax_mask_kernel(float* __restrict__ scores, const int* __restrict__ mask)
{
    const int b = blockIdx.y;
    const int q = blockIdx.x;
    float* row = scores + ((long long)b * SEQ + q) * SEQ;
    const int* mrow = mask + (long long)b * SEQ;

    const int tid = threadIdx.x;
    float vals[8];
    float mx = -CUDART_INF_F;
#pragma unroll
    for (int i = 0; i < 8; i++) {
        int idx = tid + i * 256;
        float v = row[idx];
        if (mrow[idx] == 0) v = -CUDART_INF_F;
        vals[i] = v;
        mx = fmaxf(mx, v);
    }

    __shared__ float sred[8];
    float wm = warp_max(mx);
    if ((tid & 31) == 0) sred[tid >> 5] = wm;
    __syncthreads();
    float bm = (tid < 8) ? sred[tid] : -CUDART_INF_F;
    bm = warp_max(bm);
    __shared__ float s_bm;
    if (tid == 0) s_bm = bm;
    __syncthreads();
    bm = s_bm;

    float sum = 0.f;
#pragma unroll
    for (int i = 0; i < 8; i++) {
        float e = (vals[i] == -CUDART_INF_F) ? 0.f : expf(vals[i] - bm);
        vals[i] = e;
        sum += e;
    }
    float ws = warp_sum(sum);
    if ((tid & 31) == 0) sred[tid >> 5] = ws;
    __syncthreads();
    float bs = (tid < 8) ? sred[tid] : 0.f;
    bs = warp_sum(bs);
    __shared__ float s_bs;
    if (tid == 0) s_bs = bs;
    __syncthreads();
    float inv = 1.f / s_bs;

#pragma unroll
    for (int i = 0; i < 8; i++) {
        int idx = tid + i * 256;
        row[idx] = vals[i] * inv;
    }
}

// ---------------------------------------------------------------------------
// kernel_launch
// inputs (metadata order): value, key, query, mask, Wv, Wk, Wq, Wo, bo
// ---------------------------------------------------------------------------
extern "C" void kernel_launch(void* const* d_in, const int* in_sizes, int n_in,
                              void* d_out, int out_size)
{
    const float* value = (const float*)d_in[0];
    const float* key   = (const float*)d_in[1];
    const float* query = (const float*)d_in[2];
    const int*   mask  = (const int*)d_in[3];
    const float* Wv    = (const float*)d_in[4];
    const float* Wk    = (const float*)d_in[5];
    const float* Wq    = (const float*)d_in[6];
    const float* Wo    = (const float*)d_in[7];
    const float* bo    = (const float*)d_in[8];
    float* out = (float*)d_out;

    float *pv, *pk, *pq, *ps, *pc;
    cudaGetSymbolAddress((void**)&pv, g_v);
    cudaGetSymbolAddress((void**)&pk, g_k);
    cudaGetSymbolAddress((void**)&pq, g_q);
    cudaGetSymbolAddress((void**)&ps, g_scores);
    cudaGetSymbolAddress((void**)&pc, g_ctx);

    const int MBS = BATCH * SEQ;  // 16384
    const long long SE = (long long)SEQ * EMB;
    const long long SS = (long long)SEQ * SEQ;

    // 1-3) projections: [16384 x 768] = X[16384x768] @ W^T[768x768]
    {
        dim3 grid(EMB / BN, MBS / BM, 1);
        mma_gemm<true, false><<<grid, 256>>>(value, Wv, nullptr, pv,
            MBS, EMB, EMB, 0, 0, 0, 1.0f);
        mma_gemm<true, false><<<grid, 256>>>(key, Wk, nullptr, pk,
            MBS, EMB, EMB, 0, 0, 0, 1.0f);
        // fold the (1/sqrt(E))*(1/sqrt(E)) score scaling into q
        mma_gemm<true, false><<<grid, 256>>>(query, Wq, nullptr, pq,
            MBS, EMB, EMB, 0, 0, 0, 1.0f / (float)EMB);
    }

    // 4) scores[b] = q[b] @ k[b]^T   (batched, 2048x2048x768)
    {
        dim3 grid(SEQ / BN, SEQ / BM, BATCH);
        mma_gemm<true, false><<<grid, 256>>>(pq, pk, nullptr, ps,
            SEQ, SEQ, EMB, SE, SE, SS, 1.0f);
    }

    // 5) masked softmax, in place
    {
        dim3 grid(SEQ, BATCH);
        softmax_mask_kernel<<<grid, 256>>>(ps, mask);
    }

    // 6) ctx[b] = attn[b] @ v[b]   (batched, 2048x768x2048, B not transposed)
    {
        dim3 grid(EMB / BN, SEQ / BM, BATCH);
        mma_gemm<false, false><<<grid, 256>>>(ps, pv, nullptr, pc,
            SEQ, EMB, SEQ, SS, SE, SE, 1.0f);
    }

    // 7) out = ctx @ Wo^T + bo
    {
        dim3 grid(EMB / BN, MBS / BM, 1);
        mma_gemm<true, true><<<grid, 256>>>(pc, Wo, bo, out,
            MBS, EMB, EMB, 0, 0, 0, 1.0f);
    }
}

// round 5
// speedup vs baseline: 3.2331x; 1.0807x over previous
#include <cuda_runtime.h>
#include <cuda_bf16.h>
#include <math_constants.h>
#include <cstdint>

// Problem constants
#define BATCH 8
#define SEQ   2048
#define EMB   768

// Scratch (device globals: allowed; no runtime allocation)
__device__ float g_v[(long long)BATCH * SEQ * EMB];
__device__ float g_k[(long long)BATCH * SEQ * EMB];
__device__ float g_q[(long long)BATCH * SEQ * EMB];
__device__ float g_scores[(long long)BATCH * SEQ * SEQ];
__device__ float g_ctx[(long long)BATCH * SEQ * EMB];
// tf32-rounded copies of inputs (3x [B*S*E]) and weights (4x [E*E])
__device__ float g_xin[3LL * BATCH * SEQ * EMB];
__device__ float g_wt[4LL * EMB * EMB];

__device__ __forceinline__ uint32_t f2tf32(float x) {
    uint32_t r;
    asm("cvt.rna.tf32.f32 %0, %1;" : "=r"(r) : "f"(x));
    return r;
}
__device__ __forceinline__ float tf32r(float x) {
    return __uint_as_float(f2tf32(x));
}

__device__ __forceinline__ void mma8(float* c, const uint32_t* a, const uint32_t* b) {
    asm volatile(
        "mma.sync.aligned.m16n8k8.row.col.f32.tf32.tf32.f32 "
        "{%0,%1,%2,%3}, {%4,%5,%6,%7}, {%8,%9}, {%0,%1,%2,%3};\n"
        : "+f"(c[0]), "+f"(c[1]), "+f"(c[2]), "+f"(c[3])
        : "r"(a[0]), "r"(a[1]), "r"(a[2]), "r"(a[3]), "r"(b[0]), "r"(b[1]));
}

__device__ __forceinline__ void cp16(uint32_t dst, const void* src) {
    asm volatile("cp.async.cg.shared.global [%0], [%1], 16;\n" :: "r"(dst), "l"(src));
}

// ---------------------------------------------------------------------------
// tf32 tensor-core GEMM v2: C = alpha * A @ B' (+ bias)
// Operands MUST already be tf32-rounded floats (mainloop does no cvt).
//   TRANSB=true : B is [N,K] row-major;  TRANSB=false: B is [K,N] row-major
// Block tile 256x128, BK=32, 256 threads = 8 warps (4 x 2), warp tile 64x64.
// 2-stage cp.async double buffer in dynamic smem.
// Requires M%256==0, N%128==0, K%32==0 (true for all uses here).
// ---------------------------------------------------------------------------
#define BM 256
#define BN 128
#define BK 32

template <bool TRANSB>
struct SmemCfg {
    static constexpr int AS_STR = BK + 4;                       // 36 words/row
    static constexpr int BS_STR = TRANSB ? (BK + 4) : (BN + 8); // 36 or 136
    static constexpr int ASZ = BM * AS_STR;                     // words
    static constexpr int BSZ = TRANSB ? (BN * (BK + 4)) : (BK * (BN + 8));
    static constexpr int STAGE = ASZ + BSZ;                     // words
    static constexpr int BYTES = 2 * STAGE * 4;
};

template <bool TRANSB, bool BIAS, bool CVTOUT>
__global__ __launch_bounds__(256, 1)
void mma_gemm(const float* __restrict__ A, const float* __restrict__ B,
              const float* __restrict__ bias, float* __restrict__ C,
              int M, int N, int K,
              long long sA, long long sB, long long sC, float alpha)
{
    using CFG = SmemCfg<TRANSB>;
    extern __shared__ uint32_t sm[];

    const long long bz = blockIdx.z;
    A += bz * sA;
    B += bz * sB;
    C += bz * sC;

    const int tid  = threadIdx.x;
    const int lane = tid & 31;
    const int wid  = tid >> 5;
    const int g    = lane >> 2;
    const int t4   = lane & 3;
    const int m0w  = (wid & 3) * 64;   // 4 warps along M
    const int n0w  = (wid >> 2) * 64;  // 2 warps along N
    const int row0 = blockIdx.y * BM;
    const int col0 = blockIdx.x * BN;

    float acc[4][8][4];
#pragma unroll
    for (int i = 0; i < 4; i++)
#pragma unroll
        for (int j = 0; j < 8; j++)
#pragma unroll
            for (int r = 0; r < 4; r++) acc[i][j][r] = 0.f;

    auto load_stage = [&](int s, int k0) {
        uint32_t* As = sm + s * CFG::STAGE;
        uint32_t* Bs = As + CFG::ASZ;
        // A: 256x32 floats = 2048 x 16B, 8 per thread
#pragma unroll
        for (int it = 0; it < 8; it++) {
            int idx = tid + it * 256;
            int r = idx >> 3, c4 = idx & 7;
            uint32_t d = (uint32_t)__cvta_generic_to_shared(&As[r * CFG::AS_STR + c4 * 4]);
            cp16(d, &A[(long long)(row0 + r) * K + k0 + c4 * 4]);
        }
        if (TRANSB) {
            // B [N,K]: 128x32 floats = 1024 x 16B, 4 per thread
#pragma unroll
            for (int it = 0; it < 4; it++) {
                int idx = tid + it * 256;
                int r = idx >> 3, c4 = idx & 7;
                uint32_t d = (uint32_t)__cvta_generic_to_shared(&Bs[r * CFG::BS_STR + c4 * 4]);
                cp16(d, &B[(long long)(col0 + r) * K + k0 + c4 * 4]);
            }
        } else {
            // B [K,N]: 32x128 floats, rows of 32 x 16B
#pragma unroll
            for (int it = 0; it < 4; it++) {
                int idx = tid + it * 256;
                int r = idx >> 5, c4 = idx & 31;
                uint32_t d = (uint32_t)__cvta_generic_to_shared(&Bs[r * CFG::BS_STR + c4 * 4]);
                cp16(d, &B[(long long)(k0 + r) * N + col0 + c4 * 4]);
            }
        }
    };

    auto compute = [&](int s) {
        const uint32_t* As = sm + s * CFG::STAGE;
        const uint32_t* Bs = As + CFG::ASZ;
#pragma unroll
        for (int ks = 0; ks < 4; ks++) {
            const int kk = ks * 8;
            uint32_t af[4][4];
#pragma unroll
            for (int i = 0; i < 4; i++) {
                int mr = m0w + i * 16 + g;
                af[i][0] = As[mr * CFG::AS_STR + kk + t4];
                af[i][1] = As[(mr + 8) * CFG::AS_STR + kk + t4];
                af[i][2] = As[mr * CFG::AS_STR + kk + t4 + 4];
                af[i][3] = As[(mr + 8) * CFG::AS_STR + kk + t4 + 4];
            }
            uint32_t bf[8][2];
#pragma unroll
            for (int j = 0; j < 8; j++) {
                int nc = n0w + j * 8 + g;
                if (TRANSB) {
                    bf[j][0] = Bs[nc * CFG::BS_STR + kk + t4];
                    bf[j][1] = Bs[nc * CFG::BS_STR + kk + t4 + 4];
                } else {
                    bf[j][0] = Bs[(kk + t4) * CFG::BS_STR + nc];
                    bf[j][1] = Bs[(kk + t4 + 4) * CFG::BS_STR + nc];
                }
            }
#pragma unroll
            for (int i = 0; i < 4; i++)
#pragma unroll
                for (int j = 0; j < 8; j++)
                    mma8(acc[i][j], af[i], bf[j]);
        }
    };

    const int nk = K / BK;
    load_stage(0, 0);
    asm volatile("cp.async.commit_group;\n");
    for (int kt = 0; kt < nk; kt++) {
        if (kt + 1 < nk) {
            load_stage((kt + 1) & 1, (kt + 1) * BK);
            asm volatile("cp.async.commit_group;\n");
            asm volatile("cp.async.wait_group 1;\n");
        } else {
            asm volatile("cp.async.wait_group 0;\n");
        }
        __syncthreads();
        compute(kt & 1);
        __syncthreads();
    }

    // --- epilogue
#pragma unroll
    for (int i = 0; i < 4; i++) {
        int r = row0 + m0w + i * 16 + g;
#pragma unroll
        for (int j = 0; j < 8; j++) {
            int c = col0 + n0w + j * 8 + t4 * 2;
            float2 v0, v1;
            v0.x = acc[i][j][0] * alpha;
            v0.y = acc[i][j][1] * alpha;
            v1.x = acc[i][j][2] * alpha;
            v1.y = acc[i][j][3] * alpha;
            if (BIAS) {
                float b0 = bias[c], b1 = bias[c + 1];
                v0.x += b0; v0.y += b1;
                v1.x += b0; v1.y += b1;
            }
            if (CVTOUT) {
                v0.x = tf32r(v0.x); v0.y = tf32r(v0.y);
                v1.x = tf32r(v1.x); v1.y = tf32r(v1.y);
            }
            *reinterpret_cast<float2*>(&C[(long long)r * N + c]) = v0;
            *reinterpret_cast<float2*>(&C[(long long)(r + 8) * N + c]) = v1;
        }
    }
}

// ---------------------------------------------------------------------------
// tf32 rounding pass (for raw inputs / weights)
// ---------------------------------------------------------------------------
__global__ __launch_bounds__(256)
void cvt_tf32_kernel(const float* __restrict__ in, float* __restrict__ out, int n4)
{
    int i = blockIdx.x * blockDim.x + threadIdx.x;
    if (i < n4) {
        float4 v = reinterpret_cast<const float4*>(in)[i];
        v.x = tf32r(v.x); v.y = tf32r(v.y);
        v.z = tf32r(v.z); v.w = tf32r(v.w);
        reinterpret_cast<float4*>(out)[i] = v;
    }
}

// ---------------------------------------------------------------------------
// Masked softmax over rows of scores[b, q, :], in place. Emits tf32-rounded
// probabilities (next consumer is the AV tensor-core GEMM).
// ---------------------------------------------------------------------------
__inline__ __device__ float warp_max(float v) {
#pragma unroll
    for (int o = 16; o > 0; o >>= 1) v = fmaxf(v, __shfl_xor_sync(0xffffffffu, v, o));
    return v;
}
__inline__ __device__ float warp_sum(float v) {
#pragma unroll
    for (int o = 16; o > 0; o >>= 1) v += __shfl_xor_sync(0xffffffffu, v, o);
    return v;
}

__global__ __launch_bounds__(256)
void softmax_mask_kernel(float* __restrict__ scores, const int* __restrict__ mask)
{
    const int b = blockIdx.y;
    const int q = blockIdx.x;
    float* row = scores + ((long long)b * SEQ + q) * SEQ;
    const int* mrow = mask + (long long)b * SEQ;

    const int tid = threadIdx.x;
    float vals[8];
    float mx = -CUDART_INF_F;
#pragma unroll
    for (int i = 0; i < 8; i++) {
        int idx = tid + i * 256;
        float v = row[idx];
        if (mrow[idx] == 0) v = -CUDART_INF_F;
        vals[i] = v;
        mx = fmaxf(mx, v);
    }

    __shared__ float sred[8];
    float wm = warp_max(mx);
    if ((tid & 31) == 0) sred[tid >> 5] = wm;
    __syncthreads();
    float bm = (tid < 8) ? sred[tid] : -CUDART_INF_F;
    bm = warp_max(bm);
    __shared__ float s_bm;
    if (tid == 0) s_bm = bm;
    __syncthreads();
    bm = s_bm;

    float sum = 0.f;
#pragma unroll
    for (int i = 0; i < 8; i++) {
        float e = (vals[i] == -CUDART_INF_F) ? 0.f : expf(vals[i] - bm);
        vals[i] = e;
        sum += e;
    }
    float ws = warp_sum(sum);
    if ((tid & 31) == 0) sred[tid >> 5] = ws;
    __syncthreads();
    float bs = (tid < 8) ? sred[tid] : 0.f;
    bs = warp_sum(bs);
    __shared__ float s_bs;
    if (tid == 0) s_bs = bs;
    __syncthreads();
    float inv = 1.f / s_bs;

#pragma unroll
    for (int i = 0; i < 8; i++) {
        int idx = tid + i * 256;
        row[idx] = tf32r(vals[i] * inv);
    }
}

// ---------------------------------------------------------------------------
// kernel_launch
// inputs (metadata order): value, key, query, mask, Wv, Wk, Wq, Wo, bo
// ---------------------------------------------------------------------------
extern "C" void kernel_launch(void* const* d_in, const int* in_sizes, int n_in,
                              void* d_out, int out_size)
{
    const float* value = (const float*)d_in[0];
    const float* key   = (const float*)d_in[1];
    const float* query = (const float*)d_in[2];
    const int*   mask  = (const int*)d_in[3];
    const float* Wv    = (const float*)d_in[4];
    const float* Wk    = (const float*)d_in[5];
    const float* Wq    = (const float*)d_in[6];
    const float* Wo    = (const float*)d_in[7];
    const float* bo    = (const float*)d_in[8];
    float* out = (float*)d_out;

    float *pv, *pk, *pq, *ps, *pc, *px, *pw;
    cudaGetSymbolAddress((void**)&pv, g_v);
    cudaGetSymbolAddress((void**)&pk, g_k);
    cudaGetSymbolAddress((void**)&pq, g_q);
    cudaGetSymbolAddress((void**)&ps, g_scores);
    cudaGetSymbolAddress((void**)&pc, g_ctx);
    cudaGetSymbolAddress((void**)&px, g_xin);
    cudaGetSymbolAddress((void**)&pw, g_wt);

    const int MBS = BATCH * SEQ;  // 16384
    const long long SE = (long long)SEQ * EMB;
    const long long SS = (long long)SEQ * SEQ;
    const long long XN = (long long)BATCH * SEQ * EMB;  // 12.6M
    const long long WN = (long long)EMB * EMB;

    constexpr int SMEM_T  = SmemCfg<true>::BYTES;   // 110592
    constexpr int SMEM_NN = SmemCfg<false>::BYTES;  // 108544
    cudaFuncSetAttribute(mma_gemm<true,  false, true >, cudaFuncAttributeMaxDynamicSharedMemorySize, SMEM_T);
    cudaFuncSetAttribute(mma_gemm<true,  false, false>, cudaFuncAttributeMaxDynamicSharedMemorySize, SMEM_T);
    cudaFuncSetAttribute(mma_gemm<false, false, true >, cudaFuncAttributeMaxDynamicSharedMemorySize, SMEM_NN);
    cudaFuncSetAttribute(mma_gemm<true,  true,  false>, cudaFuncAttributeMaxDynamicSharedMemorySize, SMEM_T);

    // 0) tf32-round raw inputs and weights
    {
        int n4x = (int)(XN / 4);
        int n4w = (int)(WN / 4);
        cvt_tf32_kernel<<<(n4x + 255) / 256, 256>>>(value, px + 0 * XN, n4x);
        cvt_tf32_kernel<<<(n4x + 255) / 256, 256>>>(key,   px + 1 * XN, n4x);
        cvt_tf32_kernel<<<(n4x + 255) / 256, 256>>>(query, px + 2 * XN, n4x);
        cvt_tf32_kernel<<<(n4w + 255) / 256, 256>>>(Wv, pw + 0 * WN, n4w);
        cvt_tf32_kernel<<<(n4w + 255) / 256, 256>>>(Wk, pw + 1 * WN, n4w);
        cvt_tf32_kernel<<<(n4w + 255) / 256, 256>>>(Wq, pw + 2 * WN, n4w);
        cvt_tf32_kernel<<<(n4w + 255) / 256, 256>>>(Wo, pw + 3 * WN, n4w);
    }

    // 1-3) projections: [16384 x 768] = X @ W^T  (tf32-rounded outputs)
    {
        dim3 grid(EMB / BN, MBS / BM, 1);
        mma_gemm<true, false, true><<<grid, 256, SMEM_T>>>(px + 0 * XN, pw + 0 * WN, nullptr, pv,
            MBS, EMB, EMB, 0, 0, 0, 1.0f);
        mma_gemm<true, false, true><<<grid, 256, SMEM_T>>>(px + 1 * XN, pw + 1 * WN, nullptr, pk,
            MBS, EMB, EMB, 0, 0, 0, 1.0f);
        // fold the (1/sqrt(E))*(1/sqrt(E)) score scaling into q
        mma_gemm<true, false, true><<<grid, 256, SMEM_T>>>(px + 2 * XN, pw + 2 * WN, nullptr, pq,
            MBS, EMB, EMB, 0, 0, 0, 1.0f / (float)EMB);
    }

    // 4) scores[b] = q[b] @ k[b]^T   (batched, fp32 out)
    {
        dim3 grid(SEQ / BN, SEQ / BM, BATCH);
        mma_gemm<true, false, false><<<grid, 256, SMEM_T>>>(pq, pk, nullptr, ps,
            SEQ, SEQ, EMB, SE, SE, SS, 1.0f);
    }

    // 5) masked softmax (in place; emits tf32-rounded probs)
    {
        dim3 grid(SEQ, BATCH);
        softmax_mask_kernel<<<grid, 256>>>(ps, mask);
    }

    // 6) ctx[b] = attn[b] @ v[b]   (batched NN, tf32-rounded out)
    {
        dim3 grid(EMB / BN, SEQ / BM, BATCH);
        mma_gemm<false, false, true><<<grid, 256, SMEM_NN>>>(ps, pv, nullptr, pc,
            SEQ, EMB, SEQ, SS, SE, SE, 1.0f);
    }

    // 7) out = ctx @ Wo^T + bo  (fp32 out)
    {
        dim3 grid(EMB / BN, MBS / BM, 1);
        mma_gemm<true, true, false><<<grid, 256, SMEM_T>>>(pc, pw + 3 * WN, bo, out,
            MBS, EMB, EMB, 0, 0, 0, 1.0f);
    }
}

// round 8
// speedup vs baseline: 6.5661x; 2.0309x over previous
#include <cuda_runtime.h>
#include <cuda_fp16.h>
#include <math_constants.h>
#include <cstdint>

// Problem constants
#define BATCH 8
#define SEQ   2048
#define EMB   768

// Scratch (device globals; no runtime allocation)
__device__ __half hg_x[3LL * BATCH * SEQ * EMB];     // fp16 inputs (value,key,query)
__device__ __half hg_w[4LL * EMB * EMB];             // fp16 weights (Wv,Wk,Wq,Wo)
__device__ __half hg_q[(long long)BATCH * SEQ * EMB];
__device__ __half hg_k[(long long)BATCH * SEQ * EMB];
__device__ __half hg_v[(long long)BATCH * SEQ * EMB];
__device__ __half hg_vt[(long long)BATCH * SEQ * EMB];   // V^T: [B][E][S]
__device__ float  g_scores[(long long)BATCH * SEQ * SEQ];
__device__ __half hg_probs[(long long)BATCH * SEQ * SEQ];
__device__ __half hg_ctx[(long long)BATCH * SEQ * EMB];

__device__ __forceinline__ void cp16(uint32_t dst, const void* src) {
    asm volatile("cp.async.cg.shared.global [%0], [%1], 16;\n" :: "r"(dst), "l"(src));
}

// ---------------------------------------------------------------------------
// fp16 tensor-core GEMM (TRANSB): C[m,n] = alpha * sum_k A[m,k]*B[n,k] (+bias)
//   A: [M][K] fp16 row-major, B: [N][K] fp16 row-major.
// CTA 128x128, BK=64, 256 threads = 8 warps (4 along M x 2 along N),
// warp tile 32x64 via m16n8k16 HMMA, fp32 accum.
// SW128 XOR-swizzled smem (128B rows), ldmatrix.x4 fragment loads,
// 3-stage cp.async pipeline, one __syncthreads per k-tile. 2 CTAs/SM.
// Requires M%128==0, N%128==0, K%64==0 (all uses satisfy this).
// ---------------------------------------------------------------------------
#define BM 128
#define BN 128
#define BK 64
#define NSTAGE 3

static constexpr int A_BYTES = BM * 128;             // 16 KB (128 rows x 128B)
static constexpr int B_BYTES = BN * 128;             // 16 KB
static constexpr int STAGE_BYTES = A_BYTES + B_BYTES; // 32 KB
static constexpr int SMEM_BYTES = NSTAGE * STAGE_BYTES; // 96 KB

__device__ __forceinline__ void ldsm4(uint32_t* r, uint32_t addr) {
    asm volatile("ldmatrix.sync.aligned.m8n8.x4.shared.b16 {%0,%1,%2,%3}, [%4];"
                 : "=r"(r[0]), "=r"(r[1]), "=r"(r[2]), "=r"(r[3]) : "r"(addr));
}
__device__ __forceinline__ void hmma(float* c, const uint32_t* a, const uint32_t* b) {
    asm volatile(
        "mma.sync.aligned.m16n8k16.row.col.f32.f16.f16.f32 "
        "{%0,%1,%2,%3}, {%4,%5,%6,%7}, {%8,%9}, {%0,%1,%2,%3};\n"
        : "+f"(c[0]), "+f"(c[1]), "+f"(c[2]), "+f"(c[3])
        : "r"(a[0]), "r"(a[1]), "r"(a[2]), "r"(a[3]), "r"(b[0]), "r"(b[1]));
}

template <bool BIAS, bool HALFOUT>
__global__ __launch_bounds__(256, 2)
void hgemm(const __half* __restrict__ A, const __half* __restrict__ B,
           const float* __restrict__ bias, void* __restrict__ Cv,
           int M, int N, int K, long long sA, long long sB, long long sC,
           float alpha)
{
    extern __shared__ uint8_t smem[];
    const uint32_t sbase = (uint32_t)__cvta_generic_to_shared(smem);

    const long long bz = blockIdx.z;
    A += bz * sA;
    B += bz * sB;
    const int tid  = threadIdx.x;
    const int lane = tid & 31;
    const int wid  = tid >> 5;
    const int g    = lane >> 2;
    const int t4   = lane & 3;
    const int m0   = (wid & 3) * 32;    // 4 warps along M
    const int n0   = (wid >> 2) * 64;   // 2 warps along N
    const int row0 = blockIdx.y * BM;
    const int col0 = blockIdx.x * BN;

    // ldmatrix per-lane row addressing (constant per thread)
    const int mat = lane >> 3;          // 0..3
    const int lr  = lane & 7;
    int aoff[2], arx[2];
#pragma unroll
    for (int i = 0; i < 2; i++) {
        int row = m0 + i * 16 + (mat & 1) * 8 + lr;
        aoff[i] = row * 128;
        arx[i]  = row & 7;
    }
    const int aku = mat >> 1;
    int boff[4], brx[4];
#pragma unroll
    for (int jj = 0; jj < 4; jj++) {
        int row = n0 + (2 * jj + (mat >> 1)) * 8 + lr;
        boff[jj] = row * 128;
        brx[jj]  = row & 7;
    }
    const int bku = mat & 1;

    float acc[2][8][4];
#pragma unroll
    for (int i = 0; i < 2; i++)
#pragma unroll
        for (int j = 0; j < 8; j++)
#pragma unroll
            for (int r = 0; r < 4; r++) acc[i][j][r] = 0.f;

    auto load_stage = [&](int s, int k0) {
        const uint32_t as = sbase + s * STAGE_BYTES;
        const uint32_t bs = as + A_BYTES;
        // A: 128 rows x 64 halfs = 1024 x 16B units, 4 per thread
#pragma unroll
        for (int it = 0; it < 4; it++) {
            int idx = tid + it * 256;
            int r = idx >> 3, u = idx & 7;
            cp16(as + r * 128 + ((u ^ (r & 7)) << 4),
                 A + (long long)(row0 + r) * K + k0 + u * 8);
        }
#pragma unroll
        for (int it = 0; it < 4; it++) {
            int idx = tid + it * 256;
            int r = idx >> 3, u = idx & 7;
            cp16(bs + r * 128 + ((u ^ (r & 7)) << 4),
                 B + (long long)(col0 + r) * K + k0 + u * 8);
        }
        asm volatile("cp.async.commit_group;\n");
    };

    const int nk = K / BK;
    load_stage(0, 0);
    if (nk > 1) load_stage(1, BK);

    for (int t = 0; t < nk; t++) {
        const int s = t % NSTAGE;
        if (t < nk - 1) asm volatile("cp.async.wait_group 1;\n");
        else            asm volatile("cp.async.wait_group 0;\n");
        __syncthreads();
        if (t + 2 < nk) load_stage((t + 2) % NSTAGE, (t + 2) * BK);

        const uint32_t as = sbase + s * STAGE_BYTES;
        const uint32_t bs = as + A_BYTES;
#pragma unroll
        for (int ks = 0; ks < 4; ks++) {
            uint32_t a[2][4];
#pragma unroll
            for (int i = 0; i < 2; i++)
                ldsm4(a[i], as + aoff[i] + (((2 * ks + aku) ^ arx[i]) << 4));
            uint32_t b[8][2];
#pragma unroll
            for (int jj = 0; jj < 4; jj++) {
                uint32_t r4[4];
                ldsm4(r4, bs + boff[jj] + (((2 * ks + bku) ^ brx[jj]) << 4));
                b[2 * jj][0] = r4[0]; b[2 * jj][1] = r4[1];
                b[2 * jj + 1][0] = r4[2]; b[2 * jj + 1][1] = r4[3];
            }
#pragma unroll
            for (int i = 0; i < 2; i++)
#pragma unroll
                for (int j = 0; j < 8; j++)
                    hmma(acc[i][j], a[i], b[j]);
        }
    }

    // epilogue
#pragma unroll
    for (int i = 0; i < 2; i++) {
        const int r = row0 + m0 + i * 16 + g;
#pragma unroll
        for (int j = 0; j < 8; j++) {
            const int c = col0 + n0 + j * 8 + t4 * 2;
            float v0 = acc[i][j][0] * alpha, v1 = acc[i][j][1] * alpha;
            float v2 = acc[i][j][2] * alpha, v3 = acc[i][j][3] * alpha;
            if (BIAS) {
                float b0 = bias[c], b1 = bias[c + 1];
                v0 += b0; v1 += b1; v2 += b0; v3 += b1;
            }
            if (HALFOUT) {
                __half* C = (__half*)Cv + bz * sC;
                *reinterpret_cast<__half2*>(&C[(long long)r * N + c]) =
                    __floats2half2_rn(v0, v1);
                *reinterpret_cast<__half2*>(&C[(long long)(r + 8) * N + c]) =
                    __floats2half2_rn(v2, v3);
            } else {
                float* C = (float*)Cv + bz * sC;
                *reinterpret_cast<float2*>(&C[(long long)r * N + c]) =
                    make_float2(v0, v1);
                *reinterpret_cast<float2*>(&C[(long long)(r + 8) * N + c]) =
                    make_float2(v2, v3);
            }
        }
    }
}

// ---------------------------------------------------------------------------
// fp32 -> fp16 conversion
// ---------------------------------------------------------------------------
__global__ __launch_bounds__(256)
void cvt_half_kernel(const float* __restrict__ in, __half* __restrict__ out, int n4)
{
    int i = blockIdx.x * blockDim.x + threadIdx.x;
    if (i < n4) {
        float4 v = reinterpret_cast<const float4*>(in)[i];
        __half2 h0 = __floats2half2_rn(v.x, v.y);
        __half2 h1 = __floats2half2_rn(v.z, v.w);
        uint2 u;
        u.x = *reinterpret_cast<uint32_t*>(&h0);
        u.y = *reinterpret_cast<uint32_t*>(&h1);
        reinterpret_cast<uint2*>(out)[i] = u;
    }
}

// ---------------------------------------------------------------------------
// V transpose: [B*S][E] fp16 -> [B][E][S] fp16 (64x64 tiles)
// ---------------------------------------------------------------------------
__global__ __launch_bounds__(256)
void transpose_v_kernel(const __half* __restrict__ in, __half* __restrict__ out)
{
    __shared__ __half t[64][80];
    const int b = blockIdx.z;
    const int e0 = blockIdx.x * 64;
    const int s0 = blockIdx.y * 64;
    const int tid = threadIdx.x;

    const __half* src = in + ((long long)b * SEQ + s0) * EMB + e0;
#pragma unroll
    for (int it = 0; it < 2; it++) {
        int u = tid + it * 256;
        int r = u >> 3, c = u & 7;
        uint4 v = *reinterpret_cast<const uint4*>(src + (long long)r * EMB + c * 8);
        *reinterpret_cast<uint4*>(&t[r][c * 8]) = v;
    }
    __syncthreads();
    __half* dst = out + ((long long)b * EMB + e0) * SEQ + s0;
#pragma unroll
    for (int it = 0; it < 2; it++) {
        int u = tid + it * 256;
        int er = u >> 3, c = u & 7;
        __half tmp[8];
#pragma unroll
        for (int j = 0; j < 8; j++) tmp[j] = t[c * 8 + j][er];
        *reinterpret_cast<uint4*>(dst + (long long)er * SEQ + c * 8) =
            *reinterpret_cast<uint4*>(tmp);
    }
}

// ---------------------------------------------------------------------------
// Masked softmax: reads fp32 scores, writes fp16 probabilities
// ---------------------------------------------------------------------------
__inline__ __device__ float warp_max(float v) {
#pragma unroll
    for (int o = 16; o > 0; o >>= 1) v = fmaxf(v, __shfl_xor_sync(0xffffffffu, v, o));
    return v;
}
__inline__ __device__ float warp_sum(float v) {
#pragma unroll
    for (int o = 16; o > 0; o >>= 1) v += __shfl_xor_sync(0xffffffffu, v, o);
    return v;
}

__global__ __launch_bounds__(256)
void softmax_mask_kernel(const float* __restrict__ scores,
                         const int* __restrict__ mask,
                         __half* __restrict__ probs)
{
    const int b = blockIdx.y;
    const int q = blockIdx.x;
    const float* row = scores + ((long long)b * SEQ + q) * SEQ;
    __half* prow = probs + ((long long)b * SEQ + q) * SEQ;
    const int* mrow = mask + (long long)b * SEQ;

    const int tid = threadIdx.x;
    float vals[8];
    float mx = -CUDART_INF_F;
#pragma unroll
    for (int i = 0; i < 8; i++) {
        int idx = tid + i * 256;
        float v = row[idx];
        if (mrow[idx] == 0) v = -CUDART_INF_F;
        vals[i] = v;
        mx = fmaxf(mx, v);
    }

    __shared__ float sred[8];
    float wm = warp_max(mx);
    if ((tid & 31) == 0) sred[tid >> 5] = wm;
    __syncthreads();
    float bm = (tid < 8) ? sred[tid] : -CUDART_INF_F;
    bm = warp_max(bm);
    __shared__ float s_bm;
    if (tid == 0) s_bm = bm;
    __syncthreads();
    bm = s_bm;

    float sum = 0.f;
#pragma unroll
    for (int i = 0; i < 8; i++) {
        float e = (vals[i] == -CUDART_INF_F) ? 0.f : expf(vals[i] - bm);
        vals[i] = e;
        sum += e;
    }
    float ws = warp_sum(sum);
    if ((tid & 31) == 0) sred[tid >> 5] = ws;
    __syncthreads();
    float bs = (tid < 8) ? sred[tid] : 0.f;
    bs = warp_sum(bs);
    __shared__ float s_bs;
    if (tid == 0) s_bs = bs;
    __syncthreads();
    float inv = 1.f / s_bs;

#pragma unroll
    for (int i = 0; i < 8; i++) {
        int idx = tid + i * 256;
        prow[idx] = __float2half_rn(vals[i] * inv);
    }
}

// ---------------------------------------------------------------------------
// kernel_launch: value, key, query, mask, Wv, Wk, Wq, Wo, bo
// ---------------------------------------------------------------------------
extern "C" void kernel_launch(void* const* d_in, const int* in_sizes, int n_in,
                              void* d_out, int out_size)
{
    const float* value = (const float*)d_in[0];
    const float* key   = (const float*)d_in[1];
    const float* query = (const float*)d_in[2];
    const int*   mask  = (const int*)d_in[3];
    const float* Wv    = (const float*)d_in[4];
    const float* Wk    = (const float*)d_in[5];
    const float* Wq    = (const float*)d_in[6];
    const float* Wo    = (const float*)d_in[7];
    const float* bo    = (const float*)d_in[8];
    float* out = (float*)d_out;

    __half *px, *pw, *pq, *pk, *pv, *pvt, *pprobs, *pctx;
    float *ps;
    cudaGetSymbolAddress((void**)&px, hg_x);
    cudaGetSymbolAddress((void**)&pw, hg_w);
    cudaGetSymbolAddress((void**)&pq, hg_q);
    cudaGetSymbolAddress((void**)&pk, hg_k);
    cudaGetSymbolAddress((void**)&pv, hg_v);
    cudaGetSymbolAddress((void**)&pvt, hg_vt);
    cudaGetSymbolAddress((void**)&ps, g_scores);
    cudaGetSymbolAddress((void**)&pprobs, hg_probs);
    cudaGetSymbolAddress((void**)&pctx, hg_ctx);

    const int MBS = BATCH * SEQ;  // 16384
    const long long SE = (long long)SEQ * EMB;
    const long long SS = (long long)SEQ * SEQ;
    const long long XN = (long long)BATCH * SEQ * EMB;
    const long long WN = (long long)EMB * EMB;
    const float rs = 1.0f / 27.712812921102035f;  // 1/sqrt(768)

    cudaFuncSetAttribute(hgemm<false, true >, cudaFuncAttributeMaxDynamicSharedMemorySize, SMEM_BYTES);
    cudaFuncSetAttribute(hgemm<false, false>, cudaFuncAttributeMaxDynamicSharedMemorySize, SMEM_BYTES);
    cudaFuncSetAttribute(hgemm<true,  false>, cudaFuncAttributeMaxDynamicSharedMemorySize, SMEM_BYTES);

    // 0) fp32 -> fp16 inputs + weights
    {
        int n4x = (int)(XN / 4), n4w = (int)(WN / 4);
        cvt_half_kernel<<<(n4x + 255) / 256, 256>>>(value, px + 0 * XN, n4x);
        cvt_half_kernel<<<(n4x + 255) / 256, 256>>>(key,   px + 1 * XN, n4x);
        cvt_half_kernel<<<(n4x + 255) / 256, 256>>>(query, px + 2 * XN, n4x);
        cvt_half_kernel<<<(n4w + 255) / 256, 256>>>(Wv, pw + 0 * WN, n4w);
        cvt_half_kernel<<<(n4w + 255) / 256, 256>>>(Wk, pw + 1 * WN, n4w);
        cvt_half_kernel<<<(n4w + 255) / 256, 256>>>(Wq, pw + 2 * WN, n4w);
        cvt_half_kernel<<<(n4w + 255) / 256, 256>>>(Wo, pw + 3 * WN, n4w);
    }

    // 1-3) projections (fp16 out). Fold 1/sqrt(E) into both q and k.
    {
        dim3 grid(EMB / BN, MBS / BM, 1);
        hgemm<false, true><<<grid, 256, SMEM_BYTES>>>(
            px + 0 * XN, pw + 0 * WN, nullptr, pv, MBS, EMB, EMB, 0, 0, 0, 1.0f);
        hgemm<false, true><<<grid, 256, SMEM_BYTES>>>(
            px + 1 * XN, pw + 1 * WN, nullptr, pk, MBS, EMB, EMB, 0, 0, 0, rs);
        hgemm<false, true><<<grid, 256, SMEM_BYTES>>>(
            px + 2 * XN, pw + 2 * WN, nullptr, pq, MBS, EMB, EMB, 0, 0, 0, rs);
    }

    // 3b) V transpose -> [B][E][S]
    {
        dim3 grid(EMB / 64, SEQ / 64, BATCH);
        transpose_v_kernel<<<grid, 256>>>(pv, pvt);
    }

    // 4) scores[b] = q[b] @ k[b]^T  (fp32 out)
    {
        dim3 grid(SEQ / BN, SEQ / BM, BATCH);
        hgemm<false, false><<<grid, 256, SMEM_BYTES>>>(
            pq, pk, nullptr, ps, SEQ, SEQ, EMB, SE, SE, SS, 1.0f);
    }

    // 5) masked softmax -> fp16 probs
    {
        dim3 grid(SEQ, BATCH);
        softmax_mask_kernel<<<grid, 256>>>(ps, mask, pprobs);
    }

    // 6) ctx[b] = probs[b] @ (v^T[b])^T  (fp16 out)
    {
        dim3 grid(EMB / BN, SEQ / BM, BATCH);
        hgemm<false, true><<<grid, 256, SMEM_BYTES>>>(
            pprobs, pvt, nullptr, pctx, SEQ, EMB, SEQ, SS, SE, SE, 1.0f);
    }

    // 7) out = ctx @ Wo^T + bo  (fp32 out)
    {
        dim3 grid(EMB / BN, MBS / BM, 1);
        hgemm<true, false><<<grid, 256, SMEM_BYTES>>>(
            pctx, pw + 3 * WN, bo, out, MBS, EMB, EMB, 0, 0, 0, 1.0f);
    }
}

// round 9
// speedup vs baseline: 6.8583x; 1.0445x over previous
#include <cuda_runtime.h>
#include <cuda_fp16.h>
#include <math_constants.h>
#include <cstdint>

// Problem constants
#define BATCH 8
#define SEQ   2048
#define EMB   768

// Scratch (device globals; no runtime allocation)
__device__ __half hg_x[3LL * BATCH * SEQ * EMB];     // fp16 inputs (value,key,query)
__device__ __half hg_w[4LL * EMB * EMB];             // fp16 weights (Wv,Wk,Wq,Wo)
__device__ __half hg_q[(long long)BATCH * SEQ * EMB];
__device__ __half hg_k[(long long)BATCH * SEQ * EMB];
__device__ __half hg_v[(long long)BATCH * SEQ * EMB];
__device__ __half hg_vt[(long long)BATCH * SEQ * EMB];   // V^T: [B][E][S]
__device__ __half hg_probs[(long long)BATCH * SEQ * SEQ]; // unnormalized exp(scores)
__device__ float  g_rsum[(long long)BATCH * SEQ];         // row sums of probs
__device__ __half hg_ctx[(long long)BATCH * SEQ * EMB];

__device__ __forceinline__ void cp16(uint32_t dst, const void* src) {
    asm volatile("cp.async.cg.shared.global [%0], [%1], 16;\n" :: "r"(dst), "l"(src));
}

// ---------------------------------------------------------------------------
// fp16 tensor-core GEMM (TRANSB): C[m,n] = alpha * sum_k A[m,k]*B[n,k]
//   A: [M][K] fp16 row-major, B: [N][K] fp16 row-major.
// CTA 128x128, BK=64, 256 threads = 8 warps (4 along M x 2 along N),
// warp tile 32x64 via m16n8k16 HMMA, fp32 accum. SW128 XOR-swizzled smem,
// ldmatrix.x4 fragment loads, 3-stage cp.async pipeline. 2 CTAs/SM.
// Epilogue modes:
//   MODE 0: plain (+bias optional), fp16 or fp32 out
//   MODE 1: masked exp  -> out = mask[col] ? exp(acc) : 0   (fp16 out)
//   MODE 2: row divide  -> out = acc / rsum[row]            (fp16 out)
// Requires M%128==0, N%128==0, K%64==0 (all uses satisfy this).
// ---------------------------------------------------------------------------
#define BM 128
#define BN 128
#define BK 64
#define NSTAGE 3

static constexpr int A_BYTES = BM * 128;              // 16 KB
static constexpr int B_BYTES = BN * 128;              // 16 KB
static constexpr int STAGE_BYTES = A_BYTES + B_BYTES; // 32 KB
static constexpr int SMEM_BYTES = NSTAGE * STAGE_BYTES; // 96 KB

__device__ __forceinline__ void ldsm4(uint32_t* r, uint32_t addr) {
    asm volatile("ldmatrix.sync.aligned.m8n8.x4.shared.b16 {%0,%1,%2,%3}, [%4];"
                 : "=r"(r[0]), "=r"(r[1]), "=r"(r[2]), "=r"(r[3]) : "r"(addr));
}
__device__ __forceinline__ void hmma(float* c, const uint32_t* a, const uint32_t* b) {
    asm volatile(
        "mma.sync.aligned.m16n8k16.row.col.f32.f16.f16.f32 "
        "{%0,%1,%2,%3}, {%4,%5,%6,%7}, {%8,%9}, {%0,%1,%2,%3};\n"
        : "+f"(c[0]), "+f"(c[1]), "+f"(c[2]), "+f"(c[3])
        : "r"(a[0]), "r"(a[1]), "r"(a[2]), "r"(a[3]), "r"(b[0]), "r"(b[1]));
}

template <int MODE, bool BIAS, bool HALFOUT>
__global__ __launch_bounds__(256, 2)
void hgemm(const __half* __restrict__ A, const __half* __restrict__ B,
           const float* __restrict__ bias, const int* __restrict__ mask,
           const float* __restrict__ rsum, void* __restrict__ Cv,
           int M, int N, int K, long long sA, long long sB, long long sC,
           float alpha)
{
    extern __shared__ uint8_t smem[];
    const uint32_t sbase = (uint32_t)__cvta_generic_to_shared(smem);

    const long long bz = blockIdx.z;
    A += bz * sA;
    B += bz * sB;
    const int tid  = threadIdx.x;
    const int lane = tid & 31;
    const int wid  = tid >> 5;
    const int g    = lane >> 2;
    const int t4   = lane & 3;
    const int m0   = (wid & 3) * 32;    // 4 warps along M
    const int n0   = (wid >> 2) * 64;   // 2 warps along N
    const int row0 = blockIdx.y * BM;
    const int col0 = blockIdx.x * BN;

    // ldmatrix per-lane row addressing (constant per thread)
    const int mat = lane >> 3;          // 0..3
    const int lr  = lane & 7;
    int aoff[2], arx[2];
#pragma unroll
    for (int i = 0; i < 2; i++) {
        int row = m0 + i * 16 + (mat & 1) * 8 + lr;
        aoff[i] = row * 128;
        arx[i]  = row & 7;
    }
    const int aku = mat >> 1;
    int boff[4], brx[4];
#pragma unroll
    for (int jj = 0; jj < 4; jj++) {
        int row = n0 + (2 * jj + (mat >> 1)) * 8 + lr;
        boff[jj] = row * 128;
        brx[jj]  = row & 7;
    }
    const int bku = mat & 1;

    float acc[2][8][4];
#pragma unroll
    for (int i = 0; i < 2; i++)
#pragma unroll
        for (int j = 0; j < 8; j++)
#pragma unroll
            for (int r = 0; r < 4; r++) acc[i][j][r] = 0.f;

    auto load_stage = [&](int s, int k0) {
        const uint32_t as = sbase + s * STAGE_BYTES;
        const uint32_t bs = as + A_BYTES;
#pragma unroll
        for (int it = 0; it < 4; it++) {
            int idx = tid + it * 256;
            int r = idx >> 3, u = idx & 7;
            cp16(as + r * 128 + ((u ^ (r & 7)) << 4),
                 A + (long long)(row0 + r) * K + k0 + u * 8);
        }
#pragma unroll
        for (int it = 0; it < 4; it++) {
            int idx = tid + it * 256;
            int r = idx >> 3, u = idx & 7;
            cp16(bs + r * 128 + ((u ^ (r & 7)) << 4),
                 B + (long long)(col0 + r) * K + k0 + u * 8);
        }
        asm volatile("cp.async.commit_group;\n");
    };

    const int nk = K / BK;
    load_stage(0, 0);
    if (nk > 1) load_stage(1, BK);

    for (int t = 0; t < nk; t++) {
        const int s = t % NSTAGE;
        if (t < nk - 1) asm volatile("cp.async.wait_group 1;\n");
        else            asm volatile("cp.async.wait_group 0;\n");
        __syncthreads();
        if (t + 2 < nk) load_stage((t + 2) % NSTAGE, (t + 2) * BK);

        const uint32_t as = sbase + s * STAGE_BYTES;
        const uint32_t bs = as + A_BYTES;
#pragma unroll
        for (int ks = 0; ks < 4; ks++) {
            uint32_t a[2][4];
#pragma unroll
            for (int i = 0; i < 2; i++)
                ldsm4(a[i], as + aoff[i] + (((2 * ks + aku) ^ arx[i]) << 4));
            uint32_t b[8][2];
#pragma unroll
            for (int jj = 0; jj < 4; jj++) {
                uint32_t r4[4];
                ldsm4(r4, bs + boff[jj] + (((2 * ks + bku) ^ brx[jj]) << 4));
                b[2 * jj][0] = r4[0]; b[2 * jj][1] = r4[1];
                b[2 * jj + 1][0] = r4[2]; b[2 * jj + 1][1] = r4[3];
            }
#pragma unroll
            for (int i = 0; i < 2; i++)
#pragma unroll
                for (int j = 0; j < 8; j++)
                    hmma(acc[i][j], a[i], b[j]);
        }
    }

    // epilogue
#pragma unroll
    for (int i = 0; i < 2; i++) {
        const int r = row0 + m0 + i * 16 + g;
        float inv0 = 1.f, inv1 = 1.f;
        if (MODE == 2) {
            inv0 = 1.f / rsum[bz * SEQ + r];
            inv1 = 1.f / rsum[bz * SEQ + r + 8];
        }
#pragma unroll
        for (int j = 0; j < 8; j++) {
            const int c = col0 + n0 + j * 8 + t4 * 2;
            float v0 = acc[i][j][0] * alpha, v1 = acc[i][j][1] * alpha;
            float v2 = acc[i][j][2] * alpha, v3 = acc[i][j][3] * alpha;
            if (MODE == 1) {
                // key-mask + exp (no max subtraction needed: |score| < 1)
                const int mk0 = mask[bz * SEQ + c];
                const int mk1 = mask[bz * SEQ + c + 1];
                v0 = mk0 ? expf(v0) : 0.f;
                v1 = mk1 ? expf(v1) : 0.f;
                v2 = mk0 ? expf(v2) : 0.f;
                v3 = mk1 ? expf(v3) : 0.f;
            }
            if (MODE == 2) {
                v0 *= inv0; v1 *= inv0;
                v2 *= inv1; v3 *= inv1;
            }
            if (BIAS) {
                float b0 = bias[c], b1 = bias[c + 1];
                v0 += b0; v1 += b1; v2 += b0; v3 += b1;
            }
            if (HALFOUT) {
                __half* C = (__half*)Cv + bz * sC;
                *reinterpret_cast<__half2*>(&C[(long long)r * N + c]) =
                    __floats2half2_rn(v0, v1);
                *reinterpret_cast<__half2*>(&C[(long long)(r + 8) * N + c]) =
                    __floats2half2_rn(v2, v3);
            } else {
                float* C = (float*)Cv + bz * sC;
                *reinterpret_cast<float2*>(&C[(long long)r * N + c]) =
                    make_float2(v0, v1);
                *reinterpret_cast<float2*>(&C[(long long)(r + 8) * N + c]) =
                    make_float2(v2, v3);
            }
        }
    }
}

// ---------------------------------------------------------------------------
// fp32 -> fp16 conversion
// ---------------------------------------------------------------------------
__global__ __launch_bounds__(256)
void cvt_half_kernel(const float* __restrict__ in, __half* __restrict__ out, int n4)
{
    int i = blockIdx.x * blockDim.x + threadIdx.x;
    if (i < n4) {
        float4 v = reinterpret_cast<const float4*>(in)[i];
        __half2 h0 = __floats2half2_rn(v.x, v.y);
        __half2 h1 = __floats2half2_rn(v.z, v.w);
        uint2 u;
        u.x = *reinterpret_cast<uint32_t*>(&h0);
        u.y = *reinterpret_cast<uint32_t*>(&h1);
        reinterpret_cast<uint2*>(out)[i] = u;
    }
}

// ---------------------------------------------------------------------------
// V transpose: [B*S][E] fp16 -> [B][E][S] fp16 (64x64 tiles)
// ---------------------------------------------------------------------------
__global__ __launch_bounds__(256)
void transpose_v_kernel(const __half* __restrict__ in, __half* __restrict__ out)
{
    __shared__ __half t[64][80];
    const int b = blockIdx.z;
    const int e0 = blockIdx.x * 64;
    const int s0 = blockIdx.y * 64;
    const int tid = threadIdx.x;

    const __half* src = in + ((long long)b * SEQ + s0) * EMB + e0;
#pragma unroll
    for (int it = 0; it < 2; it++) {
        int u = tid + it * 256;
        int r = u >> 3, c = u & 7;
        uint4 v = *reinterpret_cast<const uint4*>(src + (long long)r * EMB + c * 8);
        *reinterpret_cast<uint4*>(&t[r][c * 8]) = v;
    }
    __syncthreads();
    __half* dst = out + ((long long)b * EMB + e0) * SEQ + s0;
#pragma unroll
    for (int it = 0; it < 2; it++) {
        int u = tid + it * 256;
        int er = u >> 3, c = u & 7;
        __half tmp[8];
#pragma unroll
        for (int j = 0; j < 8; j++) tmp[j] = t[c * 8 + j][er];
        *reinterpret_cast<uint4*>(dst + (long long)er * SEQ + c * 8) =
            *reinterpret_cast<uint4*>(tmp);
    }
}

// ---------------------------------------------------------------------------
// Row sums of probs: one warp per row (2048 fp16), fp32 accumulate
// grid = B*S/8, block = 256 (8 warps)
// ---------------------------------------------------------------------------
__global__ __launch_bounds__(256)
void rowsum_kernel(const __half* __restrict__ probs, float* __restrict__ rsum)
{
    const int wid  = threadIdx.x >> 5;
    const int lane = threadIdx.x & 31;
    const long long row = (long long)blockIdx.x * 8 + wid;
    const __half* p = probs + row * SEQ;

    float s = 0.f;
#pragma unroll
    for (int it = 0; it < 8; it++) {
        uint4 v = *reinterpret_cast<const uint4*>(p + (lane + it * 32) * 8);
        const __half2* h = reinterpret_cast<const __half2*>(&v);
#pragma unroll
        for (int j = 0; j < 4; j++) {
            float2 f = __half22float2(h[j]);
            s += f.x + f.y;
        }
    }
#pragma unroll
    for (int o = 16; o > 0; o >>= 1) s += __shfl_xor_sync(0xffffffffu, s, o);
    if (lane == 0) rsum[row] = s;
}

// ---------------------------------------------------------------------------
// kernel_launch: value, key, query, mask, Wv, Wk, Wq, Wo, bo
// ---------------------------------------------------------------------------
extern "C" void kernel_launch(void* const* d_in, const int* in_sizes, int n_in,
                              void* d_out, int out_size)
{
    const float* value = (const float*)d_in[0];
    const float* key   = (const float*)d_in[1];
    const float* query = (const float*)d_in[2];
    const int*   mask  = (const int*)d_in[3];
    const float* Wv    = (const float*)d_in[4];
    const float* Wk    = (const float*)d_in[5];
    const float* Wq    = (const float*)d_in[6];
    const float* Wo    = (const float*)d_in[7];
    const float* bo    = (const float*)d_in[8];
    float* out = (float*)d_out;

    __half *px, *pw, *pq, *pk, *pv, *pvt, *pprobs, *pctx;
    float *prsum;
    cudaGetSymbolAddress((void**)&px, hg_x);
    cudaGetSymbolAddress((void**)&pw, hg_w);
    cudaGetSymbolAddress((void**)&pq, hg_q);
    cudaGetSymbolAddress((void**)&pk, hg_k);
    cudaGetSymbolAddress((void**)&pv, hg_v);
    cudaGetSymbolAddress((void**)&pvt, hg_vt);
    cudaGetSymbolAddress((void**)&pprobs, hg_probs);
    cudaGetSymbolAddress((void**)&prsum, g_rsum);
    cudaGetSymbolAddress((void**)&pctx, hg_ctx);

    const int MBS = BATCH * SEQ;  // 16384
    const long long SE = (long long)SEQ * EMB;
    const long long SS = (long long)SEQ * SEQ;
    const long long XN = (long long)BATCH * SEQ * EMB;
    const long long WN = (long long)EMB * EMB;
    const float rs = 1.0f / 27.712812921102035f;  // 1/sqrt(768)

    cudaFuncSetAttribute(hgemm<0, false, true >, cudaFuncAttributeMaxDynamicSharedMemorySize, SMEM_BYTES);
    cudaFuncSetAttribute(hgemm<1, false, true >, cudaFuncAttributeMaxDynamicSharedMemorySize, SMEM_BYTES);
    cudaFuncSetAttribute(hgemm<2, false, true >, cudaFuncAttributeMaxDynamicSharedMemorySize, SMEM_BYTES);
    cudaFuncSetAttribute(hgemm<0, true,  false>, cudaFuncAttributeMaxDynamicSharedMemorySize, SMEM_BYTES);

    // 0) fp32 -> fp16 inputs + weights
    {
        int n4x = (int)(XN / 4), n4w = (int)(WN / 4);
        cvt_half_kernel<<<(n4x + 255) / 256, 256>>>(value, px + 0 * XN, n4x);
        cvt_half_kernel<<<(n4x + 255) / 256, 256>>>(key,   px + 1 * XN, n4x);
        cvt_half_kernel<<<(n4x + 255) / 256, 256>>>(query, px + 2 * XN, n4x);
        cvt_half_kernel<<<(n4w + 255) / 256, 256>>>(Wv, pw + 0 * WN, n4w);
        cvt_half_kernel<<<(n4w + 255) / 256, 256>>>(Wk, pw + 1 * WN, n4w);
        cvt_half_kernel<<<(n4w + 255) / 256, 256>>>(Wq, pw + 2 * WN, n4w);
        cvt_half_kernel<<<(n4w + 255) / 256, 256>>>(Wo, pw + 3 * WN, n4w);
    }

    // 1-3) projections (fp16 out). Fold 1/sqrt(E) into both q and k.
    {
        dim3 grid(EMB / BN, MBS / BM, 1);
        hgemm<0, false, true><<<grid, 256, SMEM_BYTES>>>(
            px + 0 * XN, pw + 0 * WN, nullptr, nullptr, nullptr, pv,
            MBS, EMB, EMB, 0, 0, 0, 1.0f);
        hgemm<0, false, true><<<grid, 256, SMEM_BYTES>>>(
            px + 1 * XN, pw + 1 * WN, nullptr, nullptr, nullptr, pk,
            MBS, EMB, EMB, 0, 0, 0, rs);
        hgemm<0, false, true><<<grid, 256, SMEM_BYTES>>>(
            px + 2 * XN, pw + 2 * WN, nullptr, nullptr, nullptr, pq,
            MBS, EMB, EMB, 0, 0, 0, rs);
    }

    // 3b) V transpose -> [B][E][S]
    {
        dim3 grid(EMB / 64, SEQ / 64, BATCH);
        transpose_v_kernel<<<grid, 256>>>(pv, pvt);
    }

    // 4) probs[b] = mask .* exp(q[b] @ k[b]^T)   (fused epilogue, fp16 out)
    {
        dim3 grid(SEQ / BN, SEQ / BM, BATCH);
        hgemm<1, false, true><<<grid, 256, SMEM_BYTES>>>(
            pq, pk, nullptr, mask, nullptr, pprobs,
            SEQ, SEQ, EMB, SE, SE, SS, 1.0f);
    }

    // 5) row sums of probs
    {
        rowsum_kernel<<<MBS / 8, 256>>>(pprobs, prsum);
    }

    // 6) ctx[b] = (probs[b] @ (v^T[b])^T) / rsum[row]   (fused normalize)
    {
        dim3 grid(EMB / BN, SEQ / BM, BATCH);
        hgemm<2, false, true><<<grid, 256, SMEM_BYTES>>>(
            pprobs, pvt, nullptr, nullptr, prsum, pctx,
            SEQ, EMB, SEQ, SS, SE, SE, 1.0f);
    }

    // 7) out = ctx @ Wo^T + bo  (fp32 out)
    {
        dim3 grid(EMB / BN, MBS / BM, 1);
        hgemm<0, true, false><<<grid, 256, SMEM_BYTES>>>(
            pctx, pw + 3 * WN, bo, nullptr, nullptr, out,
            MBS, EMB, EMB, 0, 0, 0, 1.0f);
    }
}